// round 1
// baseline (speedup 1.0000x reference)
#include <cuda_runtime.h>
#include <math.h>

// Problem constants (radon_forward: H=W=512, grid 1024^2, 720 angles x 768 detectors, KB J=6)
#define JW 6
#define ALPHA_C 14.04f            // 2.34 * J
#define GSZ 1024                  // G1 == G2 == 2*H
#define NANG 720
#define NDET 768
#define KPTS (NANG * NDET)
#define TWO_PI 6.283185307179586f

// Scratch (static __device__ — no runtime allocation)
__device__ float2 g_grid[GSZ * GSZ];   // padded/shifted image, then row-FFT'd in place
__device__ float2 g_specT[GSZ * GSZ];  // transposed spectrum: specT[j][i] = FFT2[i][j] / 1024
__device__ float2 g_kdata[KPTS];       // gathered nonuniform k-space samples

// ---------------------------------------------------------------------------
// I0 (modified Bessel), Abramowitz & Stegun 9.8.1 / 9.8.2, fp32.
// Used for BOTH the apodization normalizer and the KB weights, so the
// I0(alpha) factors cancel exactly across the pipeline.
// ---------------------------------------------------------------------------
__device__ __forceinline__ float i0f_dev(float z) {
    if (z < 3.75f) {
        float t = z * (1.0f / 3.75f);
        float t2 = t * t;
        return 1.0f + t2 * (3.5156229f + t2 * (3.0899424f + t2 * (1.2067492f
                     + t2 * (0.2659732f + t2 * (0.0360768f + t2 * 0.0045813f)))));
    } else {
        float ti = 3.75f / z;
        float p = 0.39894228f + ti * (0.01328592f + ti * (0.00225319f
                + ti * (-0.00157565f + ti * (0.00916281f + ti * (-0.02057706f
                + ti * (0.02635537f + ti * (-0.01647633f + ti * 0.00392377f)))))));
        return p * __expf(z) * rsqrtf(z);
    }
}

// Image-domain apodization 1/F for pixel index n in [0,512)
__device__ __forceinline__ float apod_val(int n, float i0a) {
    float u = (float)(n - 256) * (1.0f / (float)GSZ);
    float t = 3.14159265358979f * (float)JW * u;
    float arg = ALPHA_C * ALPHA_C - t * t;
    float s = sqrtf(fabsf(arg) + 1e-20f);
    float sh;
    if (arg > 0.0f) {
        float e = __expf(s);
        sh = 0.5f * (e - 1.0f / e);
    } else {
        sh = __sinf(s);
    }
    float F = (sh / s) * ((float)JW / i0a);
    return 1.0f / F;
}

// ---------------------------------------------------------------------------
// Kernel 1: apodize + center-pad + 2D ifftshift, all fused.
// grid_shifted[i][j] = apod(img) at source (ri,ci) = ((i+512)%1024-256, ...)
// ---------------------------------------------------------------------------
__global__ void build_grid_kernel(const float* __restrict__ img) {
    int j = blockIdx.x * blockDim.x + threadIdx.x;
    int i = blockIdx.y;
    int ri = ((i + 512) & (GSZ - 1)) - 256;
    int ci = ((j + 512) & (GSZ - 1)) - 256;
    float2 v = make_float2(0.0f, 0.0f);
    if (ri >= 0 && ri < 512 && ci >= 0 && ci < 512) {
        float i0a = i0f_dev(ALPHA_C);
        v.x = img[ri * 512 + ci] * apod_val(ri, i0a) * apod_val(ci, i0a);
    }
    g_grid[i * GSZ + j] = v;
}

// ---------------------------------------------------------------------------
// Shared-memory radix-2 FFT stages (input must be bit-reversed order).
// sign = -1: forward;  sign = +1: inverse (unnormalized).
// ---------------------------------------------------------------------------
__device__ __forceinline__ void fft_stages_1024(float2* s, float sign) {
    #pragma unroll
    for (int st = 0; st < 10; ++st) {
        int half = 1 << st;
        int len = half << 1;
        #pragma unroll
        for (int q = 0; q < 2; ++q) {
            int t = threadIdx.x + q * 256;
            int grp = t >> st;
            int pos = t & (half - 1);
            int ii = grp * len + pos;
            int kk = ii + half;
            float ang = sign * TWO_PI * (float)pos / (float)len;
            float sw, cw;
            __sincosf(ang, &sw, &cw);
            float2 b = s[kk];
            float2 wb = make_float2(b.x * cw - b.y * sw, b.x * sw + b.y * cw);
            float2 a = s[ii];
            s[ii] = make_float2(a.x + wb.x, a.y + wb.y);
            s[kk] = make_float2(a.x - wb.x, a.y - wb.y);
        }
        __syncthreads();
    }
}

// Kernel 2: forward FFT along rows, in place. One block per row, 256 threads.
__global__ void fft_rows_kernel() {
    __shared__ float2 s[GSZ];
    float2* base = g_grid + (size_t)blockIdx.x * GSZ;
    for (int t = threadIdx.x; t < GSZ; t += 256) {
        s[__brev(t) >> 22] = base[t];
    }
    __syncthreads();
    fft_stages_1024(s, -1.0f);
    for (int t = threadIdx.x; t < GSZ; t += 256) {
        base[t] = s[t];
    }
}

// Kernel 3: forward FFT along columns; write transposed + normalized (1/1024).
// Block j reads grid[:,j] (strided, L2-resident) and writes specT[j][:] coalesced.
__global__ void fft_cols_kernel() {
    __shared__ float2 s[GSZ];
    int col = blockIdx.x;
    for (int t = threadIdx.x; t < GSZ; t += 256) {
        s[__brev(t) >> 22] = g_grid[(size_t)t * GSZ + col];
    }
    __syncthreads();
    fft_stages_1024(s, -1.0f);
    const float scale = 1.0f / 1024.0f;
    float2* outp = g_specT + (size_t)col * GSZ;
    for (int t = threadIdx.x; t < GSZ; t += 256) {
        float2 v = s[t];
        outp[t] = make_float2(v.x * scale, v.y * scale);
    }
}

// ---------------------------------------------------------------------------
// Kernel 4: KB gridding gather. One thread per nonuniform point.
// vals[a][b] = C[ix_a][iy_b] = specT[iy_b][ix_a];  acc = sum vals*wx_a*wy_b
// ---------------------------------------------------------------------------
__global__ void gather_kernel(const float* __restrict__ ksp) {
    int p = blockIdx.x * blockDim.x + threadIdx.x;
    if (p >= KPTS) return;

    const float c = (float)GSZ / TWO_PI;
    float g1 = fmodf(ksp[p] * c, (float)GSZ);          if (g1 < 0.0f) g1 += (float)GSZ;
    float g2 = fmodf(ksp[KPTS + p] * c, (float)GSZ);   if (g2 < 0.0f) g2 += (float)GSZ;

    int b1 = (int)floorf(g1);
    int b2 = (int)floorf(g2);

    float inv_i0a = 1.0f / i0f_dev(ALPHA_C);
    float wx[JW], wy[JW];
    int ix[JW], iy[JW];
    #pragma unroll
    for (int j = 0; j < JW; ++j) {
        int p1 = b1 - 2 + j;
        float u = g1 - (float)p1;
        float xx = fmaxf(1.0f - u * u * (1.0f / 9.0f), 0.0f);
        wx[j] = i0f_dev(ALPHA_C * sqrtf(xx)) * inv_i0a;
        ix[j] = (p1 + GSZ) & (GSZ - 1);

        int p2 = b2 - 2 + j;
        float v = g2 - (float)p2;
        float yy = fmaxf(1.0f - v * v * (1.0f / 9.0f), 0.0f);
        wy[j] = i0f_dev(ALPHA_C * sqrtf(yy)) * inv_i0a;
        iy[j] = (p2 + GSZ) & (GSZ - 1);
    }

    float accx = 0.0f, accy = 0.0f;
    #pragma unroll
    for (int bb = 0; bb < JW; ++bb) {
        const float2* __restrict__ rowp = g_specT + (size_t)iy[bb] * GSZ;
        float px = 0.0f, py = 0.0f;
        #pragma unroll
        for (int aa = 0; aa < JW; ++aa) {
            float2 v = __ldg(&rowp[ix[aa]]);
            px = fmaf(v.x, wx[aa], px);
            py = fmaf(v.y, wx[aa], py);
        }
        accx = fmaf(px, wy[bb], accx);
        accy = fmaf(py, wy[bb], accy);
    }
    g_kdata[p] = make_float2(accx, accy);
}

// ---------------------------------------------------------------------------
// Kernel 5: per-angle 768-pt inverse FFT (mixed radix 3x256) with
// ifftshift (input) and fftshift (output) folded into index maps; real part.
// One block per angle, 384 threads = 3 groups x 128.
// ---------------------------------------------------------------------------
__global__ void ifft768_kernel(float* __restrict__ out) {
    __shared__ float2 sY[3][256];
    int a = blockIdx.x;
    const float2* rowin = g_kdata + (size_t)a * NDET;

    int r = threadIdx.x >> 7;      // subsequence 0..2
    int lt = threadIdx.x & 127;

    // y_r[m] = in[3m+r], in[i] = row[(i+384)%768]; store bit-reversed(m)
    for (int m = lt; m < 256; m += 128) {
        int src = (3 * m + r + 384) % NDET;
        sY[r][__brev(m) >> 24] = rowin[src];
    }
    __syncthreads();

    // 256-pt inverse FFT per group (sign +1), 128 butterflies/thread-group/stage
    #pragma unroll
    for (int st = 0; st < 8; ++st) {
        int half = 1 << st;
        int len = half << 1;
        int grp = lt >> st;
        int pos = lt & (half - 1);
        int ii = grp * len + pos;
        int kk = ii + half;
        float ang = TWO_PI * (float)pos / (float)len;   // + sign: inverse
        float sw, cw;
        __sincosf(ang, &sw, &cw);
        float2 b = sY[r][kk];
        float2 wb = make_float2(b.x * cw - b.y * sw, b.x * sw + b.y * cw);
        float2 aa = sY[r][ii];
        sY[r][ii] = make_float2(aa.x + wb.x, aa.y + wb.y);
        sY[r][kk] = make_float2(aa.x - wb.x, aa.y - wb.y);
        __syncthreads();
    }

    // Radix-3 combine: X[k] = sum_r e^{+2pi i r k/768} Y_r[k mod 256]; Re only.
    const float inv = 1.0f / 768.0f;
    for (int k = threadIdx.x; k < NDET; k += 384) {
        int k0 = k & 255;
        float re = sY[0][k0].x;
        float a1 = TWO_PI * (float)k * (1.0f / 768.0f);
        float s1, c1;
        __sincosf(a1, &s1, &c1);
        re += sY[1][k0].x * c1 - sY[1][k0].y * s1;
        float s2, c2;
        __sincosf(a1 + a1, &s2, &c2);
        re += sY[2][k0].x * c2 - sY[2][k0].y * s2;
        out[(size_t)a * NDET + ((k + 384) % NDET)] = re * inv;
    }
}

// ---------------------------------------------------------------------------
extern "C" void kernel_launch(void* const* d_in, const int* in_sizes, int n_in,
                              void* d_out, int out_size) {
    const float* img = (const float*)d_in[0];   // (1,1,512,512) fp32
    const float* ksp = (const float*)d_in[1];   // (2, 720*768) fp32
    float* out = (float*)d_out;                 // (720,768) fp32

    build_grid_kernel<<<dim3(GSZ / 256, GSZ), 256>>>(img);
    fft_rows_kernel<<<GSZ, 256>>>();
    fft_cols_kernel<<<GSZ, 256>>>();
    gather_kernel<<<(KPTS + 255) / 256, 256>>>(ksp);
    ifft768_kernel<<<NANG, 384>>>(out);
}